// round 17
// baseline (speedup 1.0000x reference)
#include <cuda_runtime.h>
#include <cuda_fp16.h>
#include <cstdint>

// ============================================================================
// Single-term fp16 mma.sync implicit-GEMM conv, round 17 (= R16 champion with
// the A operand loaded fragment-direct from global, no smem round-trip).
// D = ah*bh ; A = w*64 fp16 (epilogue * 1/64), B = x fp16, rel_err ~2.9e-4.
// A: prep emits fragments in [mt][ch][wm][kb][am][lane][16B] order; consumer
//    does ld.global.nc.v4.b32 at lane*16 -> fully coalesced (4 wf/instr, the
//    ldsm rate) -- fixes R13's strided-v8 mistake. cp.async stage removed.
// B: row-pair LDG.32 gathers w/ pre-biased offsets (R16), k-major swizzled
//    smem, ldsm.trans. Pipeline: LDG_B(ch+1) -> MMA(ch) -> STS_B(ch+1) -> bar.
// ============================================================================

#define KTOT   2304
#define KCH    72            // 2304 / 32
#define NPIMG  2916
#define OUTIMG (512*NPIMG)
#define XIMG   (256*3136)
#define XN     (32*XIMG)     // 25690112 elements

#define A_TILE      8192     // per (mt, chunk): 2 wm x 2 kb x 4 am x 32 lane x 16B
#define STAGE_BYTES 8192     // B tile only
#define OFF_KOFF    16384                  // after 2 B stages
#define SMEM_BYTES  (OFF_KOFF + KTOT*4)    // 25600

// A (scaled x64, fp16) in fragment-direct order (see header)
__device__ __align__(128) unsigned char g_afrag[4ull*72*8192];    // 2.4MB
// combined x buffer: [0,XN) = x as fp16 ; [XN,2XN) = shifted copy x[j+1]
__device__ __align__(16) __half g_x2[2ull*XN];                    // 103MB

// ---------------------------------------------------------------------------
__device__ __forceinline__ uint32_t smem_u32(const void* p) {
    uint32_t a;
    asm("{ .reg .u64 t; cvta.to.shared.u64 t, %1; cvt.u32.u64 %0, t; }"
        : "=r"(a) : "l"(p));
    return a;
}
__device__ __forceinline__ void sts32(uint32_t addr, uint32_t v) {
    asm volatile("st.shared.b32 [%0], %1;" :: "r"(addr), "r"(v));
}
__device__ __forceinline__ void ldsm4t(uint32_t a, uint32_t& r0, uint32_t& r1,
                                       uint32_t& r2, uint32_t& r3) {
    asm volatile("ldmatrix.sync.aligned.m8n8.x4.trans.shared.b16 {%0,%1,%2,%3}, [%4];"
                 : "=r"(r0), "=r"(r1), "=r"(r2), "=r"(r3) : "r"(a));
}
__device__ __forceinline__ void mma_f16(float* c, const uint32_t* a,
                                        uint32_t b0, uint32_t b1) {
    asm volatile(
        "mma.sync.aligned.m16n8k16.row.col.f32.f16.f16.f32 "
        "{%0,%1,%2,%3}, {%4,%5,%6,%7}, {%8,%9}, {%0,%1,%2,%3};"
        : "+f"(c[0]), "+f"(c[1]), "+f"(c[2]), "+f"(c[3])
        : "r"(a[0]), "r"(a[1]), "r"(a[2]), "r"(a[3]), "r"(b0), "r"(b1));
}
// A fragment load: coalesced 16B per lane
__device__ __forceinline__ void ldg128(uint32_t* a, const void* p) {
    asm volatile("ld.global.nc.v4.b32 {%0,%1,%2,%3}, [%4];"
                 : "=r"(a[0]), "=r"(a[1]), "=r"(a[2]), "=r"(a[3]) : "l"(p));
}
__device__ __forceinline__ uint32_t ldg32(const void* p) {
    uint32_t v;
    asm volatile("ld.global.nc.u32 %0, [%1];" : "=r"(v) : "l"(p));
    return v;
}
__device__ __forceinline__ void stg_cs2(float* p, float a, float b) {
    asm volatile("st.global.cs.v2.f32 [%0], {%1, %2};"
                 :: "l"(p), "f"(a), "f"(b) : "memory");
}
__device__ __forceinline__ uint32_t pack_h2(float a, float b) {
    __half ha = __float2half_rn(a), hb = __float2half_rn(b);
    return (uint32_t)*(uint16_t*)&ha | ((uint32_t)*(uint16_t*)&hb << 16);
}

// ---------------------------------------------------------------------------
// fused prep: blocks [0,25088) pack x into both halves of g_x2;
//             [25088,25664) emit A fragments (content identical to R13, which
//             passed bit-identical -- only the ADDRESS layout differs).
// ---------------------------------------------------------------------------
__global__ void prep_all(const float* __restrict__ x, const float* __restrict__ w) {
    const int b = blockIdx.x;
    if (b < 25088) {
        int i = b * 256 + threadIdx.x;               // 6422528 total
        float4 v = ((const float4*)x)[i];
        float nxt = (4 * i + 4 < XN) ? x[4 * i + 4] : 0.0f;
        ((uint2*)g_x2)[i] = make_uint2(pack_h2(v.x, v.y), pack_h2(v.z, v.w));
        ((uint2*)(g_x2 + XN))[i] = make_uint2(pack_h2(v.y, v.z), pack_h2(v.w, nxt));
    } else {
        int i = (b - 25088) * 256 + threadIdx.x;     // 147456 x 16B
        int lane = i & 31;
        int am   = (i >> 5) & 3;
        int kb   = (i >> 7) & 1;
        int wm   = (i >> 8) & 1;
        int rest = i >> 9;                           // 0..287
        int ch = rest % 72, mt = rest / 72;
        int co0 = mt * 128 + wm * 64 + am * 16 + (lane >> 2);
        int k0  = ch * 32 + kb * 16 + (lane & 3) * 2;
        const float* wp = w + (size_t)co0 * KTOT + k0;
        float2 v00 = *(const float2*)(wp);                 // a0: A[co0][k0,k0+1]
        float2 v10 = *(const float2*)(wp + 8 * KTOT);      // a1: rows +8
        float2 v01 = *(const float2*)(wp + 8);             // a2: cols +8
        float2 v11 = *(const float2*)(wp + 8 * KTOT + 8);  // a3: both +8
        uint4 frag;
        frag.x = pack_h2(v00.x * 64.f, v00.y * 64.f);
        frag.y = pack_h2(v10.x * 64.f, v10.y * 64.f);
        frag.z = pack_h2(v01.x * 64.f, v01.y * 64.f);
        frag.w = pack_h2(v11.x * 64.f, v11.y * 64.f);
        *(uint4*)(g_afrag + (size_t)i * 16) = frag;
    }
}

// ---------------------------------------------------------------------------
// B producer (unchanged from R16): rowpair LDG.32 w/ pre-biased offsets.
// ---------------------------------------------------------------------------
__device__ __forceinline__ void load_b(
    int ch, const char* xbyte, uint32_t koffs, int kslot, uint32_t (&bx)[8])
{
    const uint32_t kb4 = koffs + (uint32_t)(ch * 32 + kslot * 8) * 4;
    uint32_t kk[8];
    asm volatile("ld.shared.v4.b32 {%0,%1,%2,%3}, [%4];"
                 : "=r"(kk[0]), "=r"(kk[1]), "=r"(kk[2]), "=r"(kk[3])
                 : "r"(kb4));
    asm volatile("ld.shared.v4.b32 {%0,%1,%2,%3}, [%4];"
                 : "=r"(kk[4]), "=r"(kk[5]), "=r"(kk[6]), "=r"(kk[7])
                 : "r"(kb4 + 16));
    #pragma unroll
    for (int g = 0; g < 8; ++g)
        bx[g] = ldg32(xbyte + kk[g]);
}
__device__ __forceinline__ void store_b(
    uint32_t bufb, const uint32_t (&bx)[8], int p, int kslot)
{
    const uint32_t sB = bufb + (uint32_t)kslot * 2048;
    const uint32_t np = (uint32_t)p * 4;
    #pragma unroll
    for (int g = 0; g < 8; ++g)
        sts32(sB + (uint32_t)g * 256 + (np ^ ((uint32_t)g << 4)), bx[g]);
}

// ---------------------------------------------------------------------------
// MMA consumer on one 32-k chunk. bufb = B stage base; A fragment-direct.
// aCh = g_afrag block for (bm, ch, wm) + lane*16.
// ---------------------------------------------------------------------------
__device__ __forceinline__ void mma_chunk(
    uint32_t bufb, float (&acc)[4][4][4], const unsigned char* aCh,
    uint32_t bOff1, uint32_t bOff2)
{
    #pragma unroll
    for (int kb = 0; kb < 2; ++kb) {
        uint32_t a[16];
        const unsigned char* aP = aCh + kb * 2048;
        ldg128(a,      aP);            // am=0
        ldg128(a + 4,  aP + 512);      // am=1
        ldg128(a + 8,  aP + 1024);     // am=2
        ldg128(a + 12, aP + 1536);     // am=3

        const uint32_t bBase = bufb + (uint32_t)kb * 4096;
        uint32_t bh[8];
        ldsm4t(bBase + bOff1, bh[0], bh[1], bh[2], bh[3]);
        ldsm4t(bBase + bOff2, bh[4], bh[5], bh[6], bh[7]);

        #pragma unroll
        for (int am = 0; am < 4; ++am)
            #pragma unroll
            for (int an = 0; an < 4; ++an)
                mma_f16(acc[am][an], a + 4*am, bh[2*an], bh[2*an+1]);
    }
}

// ---------------------------------------------------------------------------
__global__ void __launch_bounds__(256, 2)
conv_mma_kernel(float* __restrict__ out)
{
    extern __shared__ char smem[];
    const uint32_t sb = smem_u32(smem);
    const int tid = threadIdx.x;
    const int bm = blockIdx.x;        // 0..3, fastest -> x gathers shared in L2
    const int bn = blockIdx.y;        // 0..728

    // im2col k -> FINAL byte offset into g_x2 (parity folded, as R16)
    for (int k = tid; k < KTOT; k += 256) {
        int ci = k / 9, r9 = k - ci * 9;
        int kh = r9 / 3, kw = r9 - kh * 3;
        uint32_t ko = (uint32_t)(ci * 3136 + kh * 56 + kw);
        uint32_t e = (ko & 1) ? ((uint32_t)XN + ko - 1) : ko;
        *(uint32_t*)(smem + OFF_KOFF + k * 4) = e * 2;
    }

    // B producer invariants (rowpair mapping)
    const int p = tid & 63, kslot = tid >> 6;
    const int ng = bn * 128 + 2 * p;                 // even
    const int bimg = ng / NPIMG;
    const int prem = ng - bimg * NPIMG;
    const int oh = prem / 54, ow = prem - oh * 54;
    const size_t idx0 = (size_t)bimg * XIMG + oh * 56 + ow;
    const char* xbyte = (const char*)g_x2 + idx0 * 2;
    const uint32_t koffs = sb + OFF_KOFF;

    // MMA invariants: warp grid 2(m) x 4(n)
    const int lane = tid & 31, wid = tid >> 5;
    const int wm = wid & 1, wn = wid >> 1;
    // A fragment base: [mt][ch][wm][kb][am][lane][16B]
    const unsigned char* aCh = g_afrag + (size_t)bm * KCH * A_TILE
                             + (size_t)wm * 4096 + (size_t)lane * 16;
    const int li = lane & 7, lgrp = lane >> 3;
    const int kLoc = li + ((lgrp & 1) << 3);
    const int nn1 = wn * 32 + ((lgrp >> 1) << 3);
    const uint32_t bOff1 = (uint32_t)kLoc * 256
                         + (((uint32_t)(2 * nn1))        ^ ((uint32_t)li << 4));
    const uint32_t bOff2 = (uint32_t)kLoc * 256
                         + (((uint32_t)(2 * (nn1 + 16))) ^ ((uint32_t)li << 4));

    float acc[4][4][4];
    #pragma unroll
    for (int i = 0; i < 4; ++i)
        #pragma unroll
        for (int j = 0; j < 4; ++j)
            #pragma unroll
            for (int r = 0; r < 4; ++r) acc[i][j][r] = 0.0f;

    __syncthreads();                      // koff table ready

    // prologue: B stage 0
    {
        uint32_t bx0[8];
        load_b(0, xbyte, koffs, kslot, bx0);
        store_b(sb, bx0, p, kslot);
    }
    __syncthreads();

    for (int ch = 0; ch < KCH; ++ch) {
        const uint32_t cur = sb + (uint32_t)(ch & 1) * STAGE_BYTES;
        const uint32_t nxt = sb + (uint32_t)((ch + 1) & 1) * STAGE_BYTES;
        const bool pre = (ch + 1 < KCH);

        uint32_t bx[8];
        if (pre)
            load_b(ch + 1, xbyte, koffs, kslot, bx);     // LDGs issue, no wait

        mma_chunk(cur, acc, aCh, bOff1, bOff2);
        aCh += A_TILE;

        if (pre)
            store_b(nxt, bx, p, kslot);                  // LDGs landed during MMA
        __syncthreads();
    }

    // epilogue: scale by 1/64; streaming stores (evict-first)
    const float s = 0.015625f;
    const int lane4 = lane >> 2, lane2 = (lane & 3) * 2;
    #pragma unroll
    for (int an = 0; an < 4; ++an) {
        const int gn = bn * 128 + wn * 32 + an * 8 + lane2;
        const int b2 = gn / NPIMG;
        const int r2 = gn - b2 * NPIMG;
        float* op = out + (size_t)b2 * OUTIMG + r2;
        #pragma unroll
        for (int am = 0; am < 4; ++am) {
            const int co = bm * 128 + wm * 64 + am * 16 + lane4;
            stg_cs2(op + (size_t)co * NPIMG,
                    acc[am][an][0] * s, acc[am][an][1] * s);
            stg_cs2(op + (size_t)(co + 8) * NPIMG,
                    acc[am][an][2] * s, acc[am][an][3] * s);
        }
    }
}

// ---------------------------------------------------------------------------
extern "C" void kernel_launch(void* const* d_in, const int* in_sizes, int n_in,
                              void* d_out, int out_size)
{
    const float* x = (const float*)d_in[0];   // [32,256,56,56]
    const float* w = (const float*)d_in[1];   // [512,256,3,3]
    float* out = (float*)d_out;               // [32,512,54,54]

    cudaFuncSetAttribute(conv_mma_kernel,
                         cudaFuncAttributeMaxDynamicSharedMemorySize, SMEM_BYTES);

    prep_all<<<25664, 256>>>(x, w);           // pack x (both halves) + A frags
    conv_mma_kernel<<<dim3(4, 729), 256, SMEM_BYTES>>>(out);
}